// round 14
// baseline (speedup 1.0000x reference)
#include <cuda_runtime.h>
#include <cstdint>

#define FULL 0xffffffffu

static constexpr int Tn = 1024;
static constexpr int Kn = 48;
static constexpr int Bn = 512;

__device__ __forceinline__ unsigned long long pack2(float lo, float hi) {
    unsigned long long r;
    asm("mov.b64 %0, {%1, %2};" : "=l"(r) : "f"(lo), "f"(hi));
    return r;
}
__device__ __forceinline__ void unpack2(unsigned long long v, float& lo, float& hi) {
    asm("mov.b64 {%0, %1}, %2;" : "=f"(lo), "=f"(hi) : "l"(v));
}
__device__ __forceinline__ unsigned long long fma2(unsigned long long a, unsigned long long b,
                                                   unsigned long long c) {
    unsigned long long d;
    asm("fma.rn.f32x2 %0, %1, %2, %3;" : "=l"(d) : "l"(a), "l"(b), "l"(c));
    return d;
}
__device__ __forceinline__ unsigned long long add2(unsigned long long a, unsigned long long b) {
    unsigned long long d;
    asm("add.rn.f32x2 %0, %1, %2;" : "=l"(d) : "l"(a), "l"(b));
    return d;
}
__device__ __forceinline__ float rcp_approx(float x) {
    float r;
    asm("rcp.approx.f32 %0, %1;" : "=f"(r) : "f"(x));
    return r;
}

__global__ void _CRF_zero_kernel(float* out) {
    if (threadIdx.x == 0) out[0] = 0.0f;
}

__global__ void __launch_bounds__(64) _CRF_15530601742419_kernel(
    const float* __restrict__ E,            // (B, T, K) emissions
    const int* __restrict__ tags,           // (B, T)
    const void* __restrict__ mask,          // (B, T) bool — layout detected at runtime
    const float* __restrict__ Tr,           // (K, K) transitions
    const float* __restrict__ Sv,           // (K,) start
    const float* __restrict__ Ev,           // (K,) end
    float* __restrict__ out)
{
    __shared__ __align__(16) float sp[2][2][Kn];   // [warp][batchslot][K]

    const int warp = threadIdx.x >> 5;   // 0..1
    const int lane = threadIdx.x & 31;
    const int wg = blockIdx.x * 2 + warp;  // 0..255
    const int bA = wg * 2;
    const int bB = bA + 1;
    const bool vhi = (lane < 16);
    const float* __restrict__ EbA = E + (size_t)bA * Tn * Kn;
    const float* __restrict__ EbB = E + (size_t)bB * Tn * Kn;

    // ---- per-batch: sequence length + gold sequence score ----
    int lenA, lenB;
    float seqA = 0.0f, seqB = 0.0f;   // complete on lane 0
    #pragma unroll 1
    for (int s = 0; s < 2; s++) {
        const int b = bA + s;
        const float* __restrict__ Eb = (s == 0) ? EbA : EbB;
        int len;
        {
            const unsigned char* mb = (const unsigned char*)mask;
            int si;
            if (mb[1] != 0) {
                const unsigned* mw = (const unsigned*)(mb + (size_t)b * Tn) + lane * 8;
                unsigned sm = 0;
                #pragma unroll
                for (int i = 0; i < 8; i++) sm = __dp4a(mw[i], 0x01010101u, sm);
                si = (int)sm;
            } else {
                const uint4* mw = (const uint4*)((const unsigned*)mask + (size_t)b * Tn) + lane * 8;
                int sm = 0;
                #pragma unroll
                for (int i = 0; i < 8; i++) {
                    uint4 q = mw[i];
                    sm += (q.x != 0) + (q.y != 0) + (q.z != 0) + (q.w != 0);
                }
                si = sm;
            }
            #pragma unroll
            for (int o = 16; o; o >>= 1) si += __shfl_xor_sync(FULL, si, o);
            len = si;
        }
        float sc = 0.0f;
        {
            const int* __restrict__ tg = tags + (size_t)b * Tn;
            #pragma unroll 4
            for (int t = lane; t < Tn; t += 32) {
                int tag = tg[t];
                float em = Eb[t * Kn + tag];
                if (t == 0)        sc += Sv[tag] + em;
                else if (t < len)  sc += Tr[tg[t - 1] * Kn + tag] + em;
            }
            #pragma unroll
            for (int o = 16; o; o >>= 1) sc += __shfl_xor_sync(FULL, sc, o);
            if (lane == 0) sc += Ev[tg[len - 1]];
        }
        if (s == 0) { lenA = len; seqA = sc; }
        else        { lenB = len; seqB = sc; }
    }

    // ---- exp(transitions) column pairs into registers (shared by both batches) ----
    unsigned long long Mlo[24], Mhi[24];
    #pragma unroll
    for (int k = 0; k < 24; k++) {
        float a0 = __expf(Tr[(2 * k) * Kn + lane]);
        float a1 = __expf(Tr[(2 * k + 1) * Kn + lane]);
        Mlo[k] = pack2(a0, a1);
        float b0 = 0.0f, b1 = 0.0f;
        if (vhi) {
            b0 = __expf(Tr[(2 * k) * Kn + lane + 32]);
            b1 = __expf(Tr[(2 * k + 1) * Kn + lane + 32]);
        }
        Mhi[k] = pack2(b0, b1);
    }

    // ---- init both recursions ----
    float pA_lo, pA_hi, CsA, CcA;
    float pB_lo, pB_hi, CsB, CcB;
    {
        float s_lo = Sv[lane] + EbA[lane];
        float s_hi = vhi ? (Sv[lane + 32] + EbA[lane + 32]) : -1e30f;
        const float s0 = __shfl_sync(FULL, s_lo, 0);
        pA_lo = __expf(s_lo - s0);
        pA_hi = vhi ? __expf(s_hi - s0) : 0.0f;
        CsA = s0; CcA = 0.0f;
    }
    {
        float s_lo = Sv[lane] + EbB[lane];
        float s_hi = vhi ? (Sv[lane + 32] + EbB[lane + 32]) : -1e30f;
        const float s0 = __shfl_sync(FULL, s_lo, 0);
        pB_lo = __expf(s_lo - s0);
        pB_hi = vhi ? __expf(s_hi - s0) : 0.0f;
        CsB = s0; CcB = 0.0f;
    }

    // ---- emission prefetch (raw, distance 2 steps, both batches) ----
    float pfA_lo[2], pfA_hi[2], pfB_lo[2], pfB_hi[2];
    #pragma unroll
    for (int u = 0; u < 2; u++) {
        int t = 1 + u;
        pfA_lo[u] = EbA[t * Kn + lane];
        pfA_hi[u] = vhi ? EbA[t * Kn + lane + 32] : 0.0f;
        pfB_lo[u] = EbB[t * Kn + lane];
        pfB_hi[u] = vhi ? EbB[t * Kn + lane + 32] : 0.0f;
    }

    float* const bufA = sp[warp][0];
    float* const bufB = sp[warp][1];

    // ---- forward recursion: fixed 1024 steps, branch-free, 2 batches/warp,
    //      A/B work MANUALLY INTERLEAVED so B's issue fills A's latency stalls ----
    #pragma unroll 1
    for (int g = 0; g < 512; g++) {
        #pragma unroll
        for (int u = 0; u < 2; u++) {
            const int t = 1 + g * 2 + u;

            // exchange (one syncwarp covers both buffers)
            bufA[lane] = pA_lo;
            bufB[lane] = pB_lo;
            if (vhi) { bufA[lane + 32] = pA_hi; bufB[lane + 32] = pB_hi; }
            __syncwarp();

            // off-chain: emission exps + prefetch refill (into sync/LDS shadow)
            const float eemA_lo = __expf(pfA_lo[u]);
            const float eemB_lo = __expf(pfB_lo[u]);
            const float eemA_hi = __expf(pfA_hi[u]);
            const float eemB_hi = __expf(pfB_hi[u]);
            int tp = t + 2; if (tp > Tn - 1) tp = Tn - 1;
            pfA_lo[u] = EbA[tp * Kn + lane];
            pfB_lo[u] = EbB[tp * Kn + lane];
            pfA_hi[u] = vhi ? EbA[tp * Kn + lane + 32] : 0.0f;
            pfB_hi[u] = vhi ? EbB[tp * Kn + lane + 32] : 0.0f;

            // renorm scalars, interleaved
            const float p00A = bufA[0];
            const float p00B = bufB[0];
            const float rA   = rcp_approx(p00A);
            const float rB   = rcp_approx(p00B);
            const float lpA  = __logf(p00A);
            const float lpB  = __logf(p00B);
            const float erA_lo = eemA_lo * rA;
            const float erB_lo = eemB_lo * rB;
            const float erA_hi = eemA_hi * rA;
            const float erB_hi = eemB_hi * rB;

            // fused matvec: statement-level A/B alternation, 96 fma2 total
            const ulonglong2* __restrict__ pbA = (const ulonglong2*)bufA;
            const ulonglong2* __restrict__ pbB = (const ulonglong2*)bufB;
            unsigned long long aA0 = 0ull, aA1 = 0ull, bA0 = 0ull, bA1 = 0ull;
            unsigned long long aB0 = 0ull, aB1 = 0ull, bB0 = 0ull, bB1 = 0ull;
            #pragma unroll
            for (int k = 0; k < 12; k++) {
                const ulonglong2 qA = pbA[k];
                const ulonglong2 qB = pbB[k];
                aA0 = fma2(qA.x, Mlo[2 * k],     aA0);
                aB0 = fma2(qB.x, Mlo[2 * k],     aB0);
                aA1 = fma2(qA.y, Mlo[2 * k + 1], aA1);
                aB1 = fma2(qB.y, Mlo[2 * k + 1], aB1);
                bA0 = fma2(qA.x, Mhi[2 * k],     bA0);
                bB0 = fma2(qB.x, Mhi[2 * k],     bB0);
                bA1 = fma2(qA.y, Mhi[2 * k + 1], bA1);
                bB1 = fma2(qB.y, Mhi[2 * k + 1], bB1);
            }

            float xA0, xA1, yA0, yA1, xB0, xB1, yB0, yB1;
            unpack2(add2(aA0, aA1), xA0, xA1);
            unpack2(add2(aB0, aB1), xB0, xB1);
            unpack2(add2(bA0, bA1), yA0, yA1);
            unpack2(add2(bB0, bB1), yB0, yB1);

            const float pnA_lo = (xA0 + xA1) * erA_lo;
            const float pnB_lo = (xB0 + xB1) * erB_lo;
            const float pnA_hi = (yA0 + yA1) * erA_hi;
            const float pnB_hi = (yB0 + yB1) * erB_hi;

            // branch-free freeze + Kahan (off-chain), interleaved
            const bool updA = (t < lenA);
            const bool updB = (t < lenB);
            pA_lo = updA ? pnA_lo : pA_lo;
            pB_lo = updB ? pnB_lo : pB_lo;
            pA_hi = updA ? (vhi ? pnA_hi : 0.0f) : pA_hi;
            pB_hi = updB ? (vhi ? pnB_hi : 0.0f) : pB_hi;
            {
                const float addA = updA ? lpA : 0.0f;
                const float addB = updB ? lpB : 0.0f;
                const float yA = addA - CcA;
                const float yB = addB - CcB;
                const float tA = CsA + yA;
                const float tB = CsB + yB;
                CcA = (tA - CsA) - yA;
                CcB = (tB - CsB) - yB;
                CsA = tA;
                CsB = tB;
            }
        }
    }

    // ---- log_z per batch; single atomic per warp ----
    {
        const float eE_lo = __expf(Ev[lane]);
        const float eE_hi = vhi ? __expf(Ev[lane + 32]) : 0.0f;
        float vA = pA_lo * eE_lo + (vhi ? pA_hi * eE_hi : 0.0f);
        float vB = pB_lo * eE_lo + (vhi ? pB_hi * eE_hi : 0.0f);
        #pragma unroll
        for (int o = 16; o; o >>= 1) {
            vA += __shfl_xor_sync(FULL, vA, o);
            vB += __shfl_xor_sync(FULL, vB, o);
        }
        if (lane == 0) {
            const float lzA = (CsA - CcA) + __logf(vA);
            const float lzB = (CsB - CcB) + __logf(vB);
            atomicAdd(out, ((lzA - seqA) + (lzB - seqB)) * (1.0f / (float)Bn));
        }
    }
}

extern "C" void kernel_launch(void* const* d_in, const int* in_sizes, int n_in,
                              void* d_out, int out_size) {
    const float* E    = (const float*)d_in[0];
    const int*   tags = (const int*)d_in[1];
    const void*  mask = (const void*)d_in[2];
    const float* Tr   = (const float*)d_in[3];
    const float* Sv   = (const float*)d_in[4];
    const float* Ev   = (const float*)d_in[5];
    float* out = (float*)d_out;

    _CRF_zero_kernel<<<1, 32>>>(out);
    _CRF_15530601742419_kernel<<<Bn / 4, 64>>>(E, tags, mask, Tr, Sv, Ev, out);
}

// round 17
// speedup vs baseline: 2.5947x; 2.5947x over previous
#include <cuda_runtime.h>
#include <cstdint>

#define FULL 0xffffffffu

static constexpr int Tn = 1024;
static constexpr int Kn = 48;
static constexpr int Bn = 512;

__device__ __forceinline__ unsigned long long pack2(float lo, float hi) {
    unsigned long long r;
    asm("mov.b64 %0, {%1, %2};" : "=l"(r) : "f"(lo), "f"(hi));
    return r;
}
__device__ __forceinline__ void unpack2(unsigned long long v, float& lo, float& hi) {
    asm("mov.b64 {%0, %1}, %2;" : "=f"(lo), "=f"(hi) : "l"(v));
}
__device__ __forceinline__ unsigned long long fma2(unsigned long long a, unsigned long long b,
                                                   unsigned long long c) {
    unsigned long long d;
    asm("fma.rn.f32x2 %0, %1, %2, %3;" : "=l"(d) : "l"(a), "l"(b), "l"(c));
    return d;
}
__device__ __forceinline__ unsigned long long add2(unsigned long long a, unsigned long long b) {
    unsigned long long d;
    asm("add.rn.f32x2 %0, %1, %2;" : "=l"(d) : "l"(a), "l"(b));
    return d;
}
__device__ __forceinline__ float rcp_approx(float x) {
    float r;
    asm("rcp.approx.f32 %0, %1;" : "=f"(r) : "f"(x));
    return r;
}

__global__ void _CRF_zero_kernel(float* out) {
    if (threadIdx.x == 0) out[0] = 0.0f;
}

__global__ void __launch_bounds__(128, 1) _CRF_15530601742419_kernel(
    const float* __restrict__ E,            // (B, T, K) emissions
    const int* __restrict__ tags,           // (B, T)
    const void* __restrict__ mask,          // (B, T) bool — layout detected at runtime
    const float* __restrict__ Tr,           // (K, K) transitions
    const float* __restrict__ Sv,           // (K,) start
    const float* __restrict__ Ev,           // (K,) end
    float* __restrict__ out)
{
    __shared__ __align__(16) float sp[4][Kn];

    const int warp = threadIdx.x >> 5;
    const int lane = threadIdx.x & 31;
    const int b = blockIdx.x * 4 + warp;
    const bool vhi = (lane < 16);
    const float* __restrict__ Eb = E + (size_t)b * Tn * Kn;

    // ---- sequence length from mask (runtime layout detection) ----
    int len;
    {
        const unsigned char* mb = (const unsigned char*)mask;
        int si;
        if (mb[1] != 0) {
            const unsigned* mw = (const unsigned*)(mb + (size_t)b * Tn) + lane * 8;
            unsigned s = 0;
            #pragma unroll
            for (int i = 0; i < 8; i++) s = __dp4a(mw[i], 0x01010101u, s);
            si = (int)s;
        } else {
            const uint4* mw = (const uint4*)((const unsigned*)mask + (size_t)b * Tn) + lane * 8;
            int s = 0;
            #pragma unroll
            for (int i = 0; i < 8; i++) {
                uint4 q = mw[i];
                s += (q.x != 0) + (q.y != 0) + (q.z != 0) + (q.w != 0);
            }
            si = s;
        }
        #pragma unroll
        for (int o = 16; o; o >>= 1) si += __shfl_xor_sync(FULL, si, o);
        len = si;
    }

    // ---- sequence score (gold path) ----
    float seq = 0.0f;
    {
        const int* __restrict__ tg = tags + (size_t)b * Tn;
        float s = 0.0f;
        #pragma unroll 4
        for (int t = lane; t < Tn; t += 32) {
            int tag = tg[t];
            float em = Eb[t * Kn + tag];
            if (t == 0)        s += Sv[tag] + em;
            else if (t < len)  s += Tr[tg[t - 1] * Kn + tag] + em;
        }
        #pragma unroll
        for (int o = 16; o; o >>= 1) s += __shfl_xor_sync(FULL, s, o);
        if (lane == 0) s += Ev[tg[len - 1]];
        seq = s; // complete on lane 0
    }

    // ---- exp(transitions) column pairs into registers ----
    // Lane owns output states j=lane (lo) and j=lane+32 (hi, valid if lane<16).
    unsigned long long Mlo[24], Mhi[24];
    #pragma unroll
    for (int k = 0; k < 24; k++) {
        float a0 = __expf(Tr[(2 * k) * Kn + lane]);
        float a1 = __expf(Tr[(2 * k + 1) * Kn + lane]);
        Mlo[k] = pack2(a0, a1);
        float b0 = 0.0f, b1 = 0.0f;
        if (vhi) {
            b0 = __expf(Tr[(2 * k) * Kn + lane + 32]);
            b1 = __expf(Tr[(2 * k + 1) * Kn + lane + 32]);
        }
        Mhi[k] = pack2(b0, b1);
    }

    // ---- init: p = exp(score0 - score0[0]),  C = score0[0] (Kahan fp32) ----
    float s_lo = Sv[lane] + Eb[lane];
    float s_hi = vhi ? (Sv[lane + 32] + Eb[lane + 32]) : -1e30f;
    const float s0 = __shfl_sync(FULL, s_lo, 0);
    float p_lo = __expf(s_lo - s0);
    float p_hi = vhi ? __expf(s_hi - s0) : 0.0f;
    float Csum = s0, Ccomp = 0.0f;

    // ---- emission prefetch pipeline (raw values, distance 4 steps) ----
    float pf_lo[4], pf_hi[4];
    #pragma unroll
    for (int u = 0; u < 4; u++) {
        int t = 1 + u;
        pf_lo[u] = Eb[t * Kn + lane];
        pf_hi[u] = vhi ? Eb[t * Kn + lane + 32] : 0.0f;
    }

    float* const buf = sp[warp];

    // ---- forward recursion: fixed 1024 steps (t = 1..1024), branch-free body.
    // Renormalization (rcp/log/Kahan) happens once per 4-step group: p stays in
    // fp32 range over 4 unnormalized steps (growth <= ~1e17), and relative
    // spread (what determines rounding) is renorm-invariant.
    #pragma unroll 1
    for (int g = 0; g < 256; g++) {
        #pragma unroll
        for (int u = 0; u < 4; u++) {
            const int t = 1 + g * 4 + u;

            // exchange first: start the serial chain immediately
            buf[lane] = p_lo;
            if (vhi) buf[lane + 32] = p_hi;
            __syncwarp();

            // off-chain work scheduled into the sync/LDS shadow:
            const float eem_lo = __expf(pf_lo[u]);
            const float eem_hi = __expf(pf_hi[u]);
            int tp = t + 4; if (tp > Tn - 1) tp = Tn - 1;
            pf_lo[u] = Eb[tp * Kn + lane];
            pf_hi[u] = vhi ? Eb[tp * Kn + lane + 32] : 0.0f;

            // renorm factors only at group start (u==0 is compile-time)
            float f_lo, f_hi, lp0 = 0.0f;
            if (u == 0) {
                const float p00 = buf[0];
                const float r   = rcp_approx(p00);
                lp0  = __logf(p00);
                f_lo = eem_lo * r;
                f_hi = eem_hi * r;
            } else {
                f_lo = eem_lo;
                f_hi = eem_hi;
            }

            // front-batched LDS.128 stream: all 12 loads issued before the fma
            // block so the wavefront queue pipelines them (kills per-k
            // short-scoreboard exposure).
            const ulonglong2* __restrict__ pb = (const ulonglong2*)buf;
            ulonglong2 q[12];
            #pragma unroll
            for (int k = 0; k < 12; k++) q[k] = pb[k];

            unsigned long long a0 = 0ull, a1 = 0ull;
            unsigned long long b0 = 0ull, b1 = 0ull;
            #pragma unroll
            for (int k = 0; k < 12; k++) {
                a0 = fma2(q[k].x, Mlo[2 * k],     a0);
                a1 = fma2(q[k].y, Mlo[2 * k + 1], a1);
                b0 = fma2(q[k].x, Mhi[2 * k],     b0);
                b1 = fma2(q[k].y, Mhi[2 * k + 1], b1);
            }
            float x0, x1, y0, y1;
            unpack2(add2(a0, a1), x0, x1);
            unpack2(add2(b0, b1), y0, y1);

            const float pn_lo = (x0 + x1) * f_lo;
            const float pn_hi = (y0 + y1) * f_hi;

            // branch-free freeze (uniform predicate); lanes>=16 hi is exact 0
            const bool upd = (t < len);
            p_lo = upd ? pn_lo : p_lo;
            p_hi = upd ? pn_hi : p_hi;

            if (u == 0) {
                // Kahan accumulation of log-offset, once per group (off-chain)
                const float add = upd ? lp0 : 0.0f;
                const float y   = add - Ccomp;
                const float tt  = Csum + y;
                Ccomp = (tt - Csum) - y;
                Csum  = tt;
            }
        }
    }

    // ---- log_z = C + log( sum_i p_i * exp(End_i) ) ----
    {
        float v = p_lo * __expf(Ev[lane]);
        if (vhi) v += p_hi * __expf(Ev[lane + 32]);
        #pragma unroll
        for (int o = 16; o; o >>= 1) v += __shfl_xor_sync(FULL, v, o);
        if (lane == 0) {
            const float log_z = (Csum - Ccomp) + __logf(v);
            atomicAdd(out, (log_z - seq) * (1.0f / (float)Bn));
        }
    }
}

extern "C" void kernel_launch(void* const* d_in, const int* in_sizes, int n_in,
                              void* d_out, int out_size) {
    const float* E    = (const float*)d_in[0];
    const int*   tags = (const int*)d_in[1];
    const void*  mask = (const void*)d_in[2];
    const float* Tr   = (const float*)d_in[3];
    const float* Sv   = (const float*)d_in[4];
    const float* Ev   = (const float*)d_in[5];
    float* out = (float*)d_out;

    _CRF_zero_kernel<<<1, 32>>>(out);
    _CRF_15530601742419_kernel<<<Bn / 4, 128>>>(E, tags, mask, Tr, Sv, Ev, out);
}